// round 2
// baseline (speedup 1.0000x reference)
#include <cuda_runtime.h>
#include <math.h>

#define BB 4
#define TT 2048
#define CC 1024
#define HH 16
#define HS 64

// Scratch (no cudaMalloc allowed): q/k/v in [B,H,T,HS], attn out in [B,T,C]
__device__ float g_q[(size_t)BB * HH * TT * HS];
__device__ float g_k[(size_t)BB * HH * TT * HS];
__device__ float g_v[(size_t)BB * HH * TT * HS];
__device__ float g_att[(size_t)BB * TT * CC];

// ---------------------------------------------------------------------------
// Kernel 1: QKV projection. grid = (M/128, 3*H). One N-tile = one head (64).
// C[128x64] = X[128x1024] * W'[1024x64], W'[c,n] = W[h, c, n] (contiguous).
// ---------------------------------------------------------------------------
__global__ __launch_bounds__(256) void qkv_kernel(
    const float* __restrict__ x,
    const float* __restrict__ Wq,
    const float* __restrict__ Wk,
    const float* __restrict__ Wv)
{
    __shared__ float As[16][128];
    __shared__ float Bs[16][64];
    const int tid  = threadIdx.x;
    const int mat  = blockIdx.y / HH;       // 0=q, 1=k, 2=v
    const int h    = blockIdx.y % HH;
    const float* W = (mat == 0 ? Wq : (mat == 1 ? Wk : Wv)) + (size_t)h * CC * HS;
    float* outb    = (mat == 0 ? g_q : (mat == 1 ? g_k : g_v));
    const int m0   = blockIdx.x * 128;
    const int mgrp = tid >> 4;              // 16 groups of 8 rows
    const int ngrp = tid & 15;              // 16 groups of 4 cols

    float acc[8][4];
    #pragma unroll
    for (int i = 0; i < 8; i++)
        #pragma unroll
        for (int j = 0; j < 4; j++) acc[i][j] = 0.f;

    for (int k0 = 0; k0 < CC; k0 += 16) {
        // Load A tile 128x16 (coalesced: 8 consecutive rows x 64B per warp)
        #pragma unroll
        for (int c = 0; c < 2; c++) {
            int idx = c * 256 + tid;
            int row = idx >> 2, kq = idx & 3;
            float4 v = *(const float4*)(x + (size_t)(m0 + row) * CC + k0 + kq * 4);
            As[kq * 4 + 0][row] = v.x;
            As[kq * 4 + 1][row] = v.y;
            As[kq * 4 + 2][row] = v.z;
            As[kq * 4 + 3][row] = v.w;
        }
        // Load B tile 16x64 (contiguous within head)
        {
            int c = tid >> 4, nq = tid & 15;
            float4 v = *(const float4*)(W + (size_t)(k0 + c) * HS + nq * 4);
            *(float4*)&Bs[c][nq * 4] = v;
        }
        __syncthreads();
        #pragma unroll
        for (int kt = 0; kt < 16; kt++) {
            float4 a0 = *(float4*)&As[kt][mgrp * 8];
            float4 a1 = *(float4*)&As[kt][mgrp * 8 + 4];
            float4 b4 = *(float4*)&Bs[kt][ngrp * 4];
            float a[8] = {a0.x, a0.y, a0.z, a0.w, a1.x, a1.y, a1.z, a1.w};
            float bb[4] = {b4.x, b4.y, b4.z, b4.w};
            #pragma unroll
            for (int i = 0; i < 8; i++)
                #pragma unroll
                for (int j = 0; j < 4; j++)
                    acc[i][j] += a[i] * bb[j];
        }
        __syncthreads();
    }
    #pragma unroll
    for (int i = 0; i < 8; i++) {
        int m = m0 + mgrp * 8 + i;
        int b_ = m >> 11, t = m & (TT - 1);
        float* p = outb + ((size_t)((b_ * HH + h) * TT + t)) * HS + ngrp * 4;
        *(float4*)p = make_float4(acc[i][0], acc[i][1], acc[i][2], acc[i][3]);
    }
}

// ---------------------------------------------------------------------------
// Kernel 2: flash attention (causal, online softmax).
// grid = (B*H, T/128). Q tile 128 x 64, KV tile 64 x 64.
// Thread map: qgrp = tid/16 (8 q rows), sgrp = tid%16 (4 s cols / 4 d cols).
// smem: Qt[d][q] 32KB | Kt[d][s] 16KB | Vs[s][d] 16KB | Pt[q][s] 32KB = 96KB
// ---------------------------------------------------------------------------
__global__ __launch_bounds__(256) void attn_kernel()
{
    extern __shared__ float sm[];
    float* Qt = sm;                 // [64][128]
    float* Kt = sm + 64 * 128;      // [64][64]
    float* Vs = Kt + 64 * 64;       // [64][64]
    float* Pt = Vs + 64 * 64;       // [128][64]

    const int tid  = threadIdx.x;
    const int bh   = blockIdx.x;                      // b*16 + h
    const int qi   = (int)(gridDim.y - 1 - blockIdx.y); // heavy tiles first
    const int b    = bh >> 4, h = bh & 15;
    const int q0g  = qi * 128;
    const int qgrp = tid >> 4;
    const int sgrp = tid & 15;

    // Load Q (transposed to d-major)
    {
        int q = tid >> 1, dbase = (tid & 1) * 32;
        const float* qp = g_q + ((size_t)bh * TT + q0g + q) * HS + dbase;
        #pragma unroll
        for (int c = 0; c < 8; c++) {
            float4 v = *(const float4*)(qp + c * 4);
            int d = dbase + c * 4;
            Qt[(d + 0) * 128 + q] = v.x;
            Qt[(d + 1) * 128 + q] = v.y;
            Qt[(d + 2) * 128 + q] = v.z;
            Qt[(d + 3) * 128 + q] = v.w;
        }
    }

    float m_run[8], l_run[8], acc[8][4];
    #pragma unroll
    for (int i = 0; i < 8; i++) {
        m_run[i] = -1e30f;
        l_run[i] = 0.f;
        #pragma unroll
        for (int j = 0; j < 4; j++) acc[i][j] = 0.f;
    }

    const int jmax = 2 * qi + 1;
    for (int j = 0; j <= jmax; j++) {
        // Load K (transposed) and V (row-major)
        {
            int s = tid >> 2, dbase = (tid & 3) * 16;
            const float* kp = g_k + ((size_t)bh * TT + j * 64 + s) * HS + dbase;
            const float* vp = g_v + ((size_t)bh * TT + j * 64 + s) * HS + dbase;
            #pragma unroll
            for (int c = 0; c < 4; c++) {
                float4 kv = *(const float4*)(kp + c * 4);
                int d = dbase + c * 4;
                Kt[(d + 0) * 64 + s] = kv.x;
                Kt[(d + 1) * 64 + s] = kv.y;
                Kt[(d + 2) * 64 + s] = kv.z;
                Kt[(d + 3) * 64 + s] = kv.w;
                *(float4*)&Vs[s * 64 + dbase + c * 4] = *(const float4*)(vp + c * 4);
            }
        }
        __syncthreads();

        // S = Q K^T  (128x64 tile, 8x4 per thread)
        float st[8][4];
        #pragma unroll
        for (int i = 0; i < 8; i++)
            #pragma unroll
            for (int jj = 0; jj < 4; jj++) st[i][jj] = 0.f;

        #pragma unroll 2
        for (int d = 0; d < 64; d++) {
            float4 k4  = *(float4*)&Kt[d * 64 + sgrp * 4];
            float4 q0v = *(float4*)&Qt[d * 128 + qgrp * 8];
            float4 q1v = *(float4*)&Qt[d * 128 + qgrp * 8 + 4];
            float qa[8] = {q0v.x, q0v.y, q0v.z, q0v.w, q1v.x, q1v.y, q1v.z, q1v.w};
            float kb[4] = {k4.x, k4.y, k4.z, k4.w};
            #pragma unroll
            for (int i = 0; i < 8; i++)
                #pragma unroll
                for (int jj = 0; jj < 4; jj++)
                    st[i][jj] += qa[i] * kb[jj];
        }

        // Online softmax update (scale = 1/sqrt(64) = 0.125)
        const bool domask = (j >= 2 * qi);
        #pragma unroll
        for (int i = 0; i < 8; i++) {
            const int tq = q0g + qgrp * 8 + i;
            float mx = -1e30f;
            #pragma unroll
            for (int jj = 0; jj < 4; jj++) {
                float v = st[i][jj] * 0.125f;
                if (domask && (j * 64 + sgrp * 4 + jj) > tq) v = -1e30f;
                st[i][jj] = v;
                mx = fmaxf(mx, v);
            }
            #pragma unroll
            for (int off = 1; off < 16; off <<= 1)
                mx = fmaxf(mx, __shfl_xor_sync(0xffffffffu, mx, off, 16));
            float mn = fmaxf(m_run[i], mx);
            float cf = __expf(m_run[i] - mn);
            m_run[i] = mn;
            float psum = 0.f;
            #pragma unroll
            for (int jj = 0; jj < 4; jj++) {
                float p = __expf(st[i][jj] - mn);
                st[i][jj] = p;
                psum += p;
            }
            #pragma unroll
            for (int off = 1; off < 16; off <<= 1)
                psum += __shfl_xor_sync(0xffffffffu, psum, off, 16);
            l_run[i] = l_run[i] * cf + psum;
            #pragma unroll
            for (int jj = 0; jj < 4; jj++) acc[i][jj] *= cf;
            *(float4*)&Pt[(qgrp * 8 + i) * 64 + sgrp * 4] =
                make_float4(st[i][0], st[i][1], st[i][2], st[i][3]);
        }
        __syncthreads();

        // O += P V  (sgrp re-used as d-group)
        #pragma unroll 2
        for (int s = 0; s < 64; s++) {
            float4 v4 = *(float4*)&Vs[s * 64 + sgrp * 4];
            #pragma unroll
            for (int i = 0; i < 8; i++) {
                float p = Pt[(qgrp * 8 + i) * 64 + s];
                acc[i][0] += p * v4.x;
                acc[i][1] += p * v4.y;
                acc[i][2] += p * v4.z;
                acc[i][3] += p * v4.w;
            }
        }
        __syncthreads();
    }

    // Normalize and write out in [B,T,C] (heads concatenated)
    #pragma unroll
    for (int i = 0; i < 8; i++) {
        float inv = 1.f / l_run[i];
        int tq = q0g + qgrp * 8 + i;
        float* op = g_att + ((size_t)(b * TT + tq)) * CC + h * HS + sgrp * 4;
        *(float4*)op = make_float4(acc[i][0] * inv, acc[i][1] * inv,
                                   acc[i][2] * inv, acc[i][3] * inv);
    }
}

// ---------------------------------------------------------------------------
// Kernel 3: output projection Y = Oc @ Wo^T + bo. grid = (M/128, N/128).
// Both A (Oc) and B (Wo) are K-contiguous row-major.
// ---------------------------------------------------------------------------
__global__ __launch_bounds__(256) void proj_kernel(
    const float* __restrict__ Wo,
    const float* __restrict__ bo,
    float* __restrict__ out)
{
    __shared__ float As[16][128];
    __shared__ float Bs[16][128];
    const int tid  = threadIdx.x;
    const int m0   = blockIdx.x * 128;
    const int n0b  = blockIdx.y * 128;
    const int mgrp = tid >> 4;
    const int ngrp = tid & 15;

    float acc[8][8];
    #pragma unroll
    for (int i = 0; i < 8; i++)
        #pragma unroll
        for (int j = 0; j < 8; j++) acc[i][j] = 0.f;

    for (int k0 = 0; k0 < CC; k0 += 16) {
        #pragma unroll
        for (int c = 0; c < 2; c++) {
            int idx = c * 256 + tid;
            int row = idx >> 2, kq = idx & 3;
            float4 v = *(const float4*)(g_att + (size_t)(m0 + row) * CC + k0 + kq * 4);
            As[kq * 4 + 0][row] = v.x;
            As[kq * 4 + 1][row] = v.y;
            As[kq * 4 + 2][row] = v.z;
            As[kq * 4 + 3][row] = v.w;
            float4 w = *(const float4*)(Wo + (size_t)(n0b + row) * CC + k0 + kq * 4);
            Bs[kq * 4 + 0][row] = w.x;
            Bs[kq * 4 + 1][row] = w.y;
            Bs[kq * 4 + 2][row] = w.z;
            Bs[kq * 4 + 3][row] = w.w;
        }
        __syncthreads();
        #pragma unroll
        for (int kt = 0; kt < 16; kt++) {
            float4 a0 = *(float4*)&As[kt][mgrp * 8];
            float4 a1 = *(float4*)&As[kt][mgrp * 8 + 4];
            float4 b0 = *(float4*)&Bs[kt][ngrp * 8];
            float4 b1 = *(float4*)&Bs[kt][ngrp * 8 + 4];
            float a[8] = {a0.x, a0.y, a0.z, a0.w, a1.x, a1.y, a1.z, a1.w};
            float bb[8] = {b0.x, b0.y, b0.z, b0.w, b1.x, b1.y, b1.z, b1.w};
            #pragma unroll
            for (int i = 0; i < 8; i++)
                #pragma unroll
                for (int j = 0; j < 8; j++)
                    acc[i][j] += a[i] * bb[j];
        }
        __syncthreads();
    }

    float4 bv0 = *(const float4*)(bo + n0b + ngrp * 8);
    float4 bv1 = *(const float4*)(bo + n0b + ngrp * 8 + 4);
    float bias[8] = {bv0.x, bv0.y, bv0.z, bv0.w, bv1.x, bv1.y, bv1.z, bv1.w};
    #pragma unroll
    for (int i = 0; i < 8; i++) {
        int m = m0 + mgrp * 8 + i;
        float* p = out + (size_t)m * CC + n0b + ngrp * 8;
        *(float4*)p = make_float4(acc[i][0] + bias[0], acc[i][1] + bias[1],
                                  acc[i][2] + bias[2], acc[i][3] + bias[3]);
        *(float4*)(p + 4) = make_float4(acc[i][4] + bias[4], acc[i][5] + bias[5],
                                        acc[i][6] + bias[6], acc[i][7] + bias[7]);
    }
}

extern "C" void kernel_launch(void* const* d_in, const int* in_sizes, int n_in,
                              void* d_out, int out_size)
{
    const float* x  = (const float*)d_in[0];
    const float* Wq = (const float*)d_in[1];
    const float* Wk = (const float*)d_in[2];
    const float* Wv = (const float*)d_in[3];
    const float* Wo = (const float*)d_in[4];
    const float* bo = (const float*)d_in[5];
    float* out = (float*)d_out;

    (void)in_sizes; (void)n_in; (void)out_size;

    // 1) QKV projections
    qkv_kernel<<<dim3(64, 48), 256>>>(x, Wq, Wk, Wv);

    // 2) Flash attention (96 KB dynamic smem)
    const int attn_smem = 96 * 1024;
    cudaFuncSetAttribute(attn_kernel, cudaFuncAttributeMaxDynamicSharedMemorySize,
                         attn_smem);
    attn_kernel<<<dim3(64, 16), 256, attn_smem>>>();

    // 3) Output projection + bias
    proj_kernel<<<dim3(64, 8), 256>>>(Wo, bo, out);
}